// round 2
// baseline (speedup 1.0000x reference)
#include <cuda_runtime.h>

#define NB   4
#define CIN  32
#define CC   64
#define NPTS 32768      // points per batch
#define V3   32768      // 32^3 voxels
#define NG   8
#define EPS  1e-5f

// ---------------- scratch (device globals; no allocation allowed) ----------
__device__ __align__(16) float g_buf1[NB * CC * NPTS];   // y / out_pre
__device__ __align__(16) float g_buf2[NB * CC * V3];     // vox_sum/vox0 ; conv2 out
__device__ __align__(16) float g_buf3[NB * CC * V3];     // conv1 out ; voxT (b,v,c)
__device__ int   g_cnt[NB * V3];
__device__ float g_bias[NB * CC];
__device__ float g_mu[NB * NG];
__device__ float g_rs[NB * NG];

__device__ __forceinline__ float siluf(float x) { return x / (1.f + __expf(-x)); }

// ---------------- K1: time bias  bias[b,o] = t_emb[b,:] @ w_time[o,:] + b_time[o]
__global__ void k_bias(const float* __restrict__ t_emb,
                       const float* __restrict__ w_time,
                       const float* __restrict__ b_time) {
    __shared__ float te[256];
    int b = blockIdx.x, o = threadIdx.x;
    for (int i = o; i < 256; i += 64) te[i] = t_emb[b * 256 + i];
    __syncthreads();
    float s = b_time[o];
    #pragma unroll 8
    for (int t = 0; t < 256; t++) s += te[t] * w_time[o * 256 + t];
    g_bias[b * CC + o] = s;
}

// ---------------- K2: y[b,o,n] = sum_c w_in[o,c] * feats[b,c,n]
__global__ void __launch_bounds__(128) k_pw_in(const float* __restrict__ feats,
                                               const float* __restrict__ w) {
    __shared__ float4 sw[CIN * 16];                 // transposed [c][o/4]
    for (int i = threadIdx.x; i < CIN * CC; i += 128) {
        int o = i >> 5, c = i & 31;
        ((float*)sw)[c * CC + o] = w[i];
    }
    __syncthreads();
    int p = blockIdx.x * 128 + threadIdx.x;         // 0 .. B*N-1
    int b = p >> 15, n = p & 32767;
    float acc[CC];
    #pragma unroll
    for (int o = 0; o < CC; o++) acc[o] = 0.f;
    #pragma unroll 4
    for (int c = 0; c < CIN; c++) {
        float x = feats[((b * CIN + c) << 15) + n];
        const float4* wr = sw + c * 16;
        #pragma unroll
        for (int q = 0; q < 16; q++) {
            float4 ww = wr[q];
            acc[q * 4 + 0] += x * ww.x; acc[q * 4 + 1] += x * ww.y;
            acc[q * 4 + 2] += x * ww.z; acc[q * 4 + 3] += x * ww.w;
        }
    }
    #pragma unroll
    for (int o = 0; o < CC; o++) g_buf1[((b * CC + o) << 15) + n] = acc[o];
}

// ---------------- GN stats: per (b,g) mean & rstd over contiguous 262144 floats
__global__ void k_stats(const float* __restrict__ buf) {
    __shared__ float ssum[256], ssq[256];
    int bg = blockIdx.x;                            // 0..31
    const float4* p = (const float4*)(buf + (size_t)bg * 262144);
    float s = 0.f, q = 0.f;
    for (int i = threadIdx.x; i < 65536; i += 256) {
        float4 v = p[i];
        s += v.x + v.y + v.z + v.w;
        q += v.x * v.x + v.y * v.y + v.z * v.z + v.w * v.w;
    }
    ssum[threadIdx.x] = s; ssq[threadIdx.x] = q;
    __syncthreads();
    for (int st = 128; st > 0; st >>= 1) {
        if (threadIdx.x < st) {
            ssum[threadIdx.x] += ssum[threadIdx.x + st];
            ssq[threadIdx.x]  += ssq[threadIdx.x + st];
        }
        __syncthreads();
    }
    if (threadIdx.x == 0) {
        float mean = ssum[0] * (1.f / 262144.f);
        float var  = ssq[0] * (1.f / 262144.f) - mean * mean;
        g_mu[bg] = mean;
        g_rs[bg] = rsqrtf(var + EPS);
    }
}

// ---------------- zero vox accumulators
__global__ void k_zero() {
    int idx = blockIdx.x * 256 + threadIdx.x;       // covers 8388608
    g_buf2[idx] = 0.f;
    if (idx < NB * V3) g_cnt[idx] = 0;
}

// ---------------- K4: GN1 + SiLU + bias, scatter-add into voxel grid
__global__ void __launch_bounds__(128) k_scatter(const float* __restrict__ coords,
                                                 const float* __restrict__ gg,
                                                 const float* __restrict__ gb) {
    int p = blockIdx.x * 128 + threadIdx.x;
    int b = p >> 15, n = p & 32767;
    float cx = coords[p * 3 + 0] * 31.f;
    float cy = coords[p * 3 + 1] * 31.f;
    float cz = coords[p * 3 + 2] * 31.f;
    int ix = min(max(__float2int_rd(cx), 0), 31);
    int iy = min(max(__float2int_rd(cy), 0), 31);
    int iz = min(max(__float2int_rd(cz), 0), 31);
    int flat = (ix << 10) + (iy << 5) + iz;
    atomicAdd(&g_cnt[(b << 15) + flat], 1);
    #pragma unroll 4
    for (int c = 0; c < CC; c++) {
        int bg = b * NG + (c >> 3);
        float x = g_buf1[((b * CC + c) << 15) + n];
        x = (x - g_mu[bg]) * g_rs[bg] * gg[c] + gb[c];
        x = siluf(x) + g_bias[b * CC + c];
        atomicAdd(&g_buf2[((b * CC + c) << 15) + flat], x);
    }
}

// ---------------- K5: vox = sum / max(cnt,1) + bias
__global__ void k_voxfin() {
    int idx = blockIdx.x * 256 + threadIdx.x;       // 8388608
    int v = idx & 32767, bc = idx >> 15;
    int b = bc >> 6;
    int cnt = g_cnt[(b << 15) + v];
    float s = g_buf2[idx];
    g_buf2[idx] = s / (float)max(cnt, 1) + g_bias[bc];
}

// ---------------- conv3d 3x3x3, 64->64 ch, SAME pad
// block: 8^3 spatial tile x 16 out-ch; 128 threads; 4 voxels x 16 oc per thread
__global__ void __launch_bounds__(128) k_conv(const float* __restrict__ in,
                                              const float* __restrict__ w,
                                              float* __restrict__ out) {
    __shared__ float s_in[8 * 1000];                // 8 ci x 10x10x10 halo
    __shared__ float s_w[16 * 216];                 // [oo][ci*27+t]
    int tile = blockIdx.x;                          // 0..63
    int txw = (tile & 3) << 3, tyh = ((tile >> 2) & 3) << 3, tzd = ((tile >> 4) & 3) << 3;
    int og = blockIdx.y, b = blockIdx.z;
    int tid = threadIdx.x;

    int sb[4], gob[4];
    #pragma unroll
    for (int k = 0; k < 4; k++) {
        int v = tid + (k << 7);
        int ld = v >> 6, lh = (v >> 3) & 7, lw = v & 7;
        sb[k]  = ld * 100 + lh * 10 + lw;
        gob[k] = ((b * CC + og * 16) << 15) + ((tzd + ld) << 10) + ((tyh + lh) << 5) + (txw + lw);
    }
    float acc[4][16];
    #pragma unroll
    for (int k = 0; k < 4; k++)
        #pragma unroll
        for (int o = 0; o < 16; o++) acc[k][o] = 0.f;

    const float* inb = in + ((b * CC) << 15);
    for (int chunk = 0; chunk < 8; chunk++) {
        __syncthreads();
        int ci0 = chunk * 8;
        for (int i = tid; i < 8000; i += 128) {
            int ci = i / 1000, r = i - ci * 1000;
            int dz = r / 100; int rr = r - dz * 100;
            int dy = rr / 10; int dx = rr - dy * 10;
            int gd = tzd + dz - 1, gh = tyh + dy - 1, gw = txw + dx - 1;
            float vv = 0.f;
            if (((unsigned)gd < 32u) && ((unsigned)gh < 32u) && ((unsigned)gw < 32u))
                vv = inb[((ci0 + ci) << 15) + (gd << 10) + (gh << 5) + gw];
            s_in[i] = vv;
        }
        for (int i = tid; i < 3456; i += 128) {
            int oo = i / 216, r = i - oo * 216;     // r = ci*27 + t
            s_w[i] = w[((og * 16 + oo) * CC + ci0) * 27 + r];
        }
        __syncthreads();
        for (int ci = 0; ci < 8; ci++) {
            const float* sI = s_in + ci * 1000;
            const float* sW = s_w + ci * 27;
            for (int kd = 0; kd < 3; kd++) {
                const float* sId = sI + kd * 100;
                const float* sWd = sW + kd * 9;
                #pragma unroll
                for (int kh = 0; kh < 3; kh++) {
                    #pragma unroll
                    for (int kw = 0; kw < 3; kw++) {
                        int toff = kh * 10 + kw;
                        int t = kh * 3 + kw;
                        float x0 = sId[sb[0] + toff], x1 = sId[sb[1] + toff];
                        float x2 = sId[sb[2] + toff], x3 = sId[sb[3] + toff];
                        #pragma unroll
                        for (int oo = 0; oo < 16; oo++) {
                            float ww = sWd[oo * 216 + t];
                            acc[0][oo] += x0 * ww; acc[1][oo] += x1 * ww;
                            acc[2][oo] += x2 * ww; acc[3][oo] += x3 * ww;
                        }
                    }
                }
            }
        }
    }
    #pragma unroll
    for (int k = 0; k < 4; k++)
        #pragma unroll
        for (int oo = 0; oo < 16; oo++)
            out[gob[k] + (oo << 15)] = acc[k][oo];
}

// ---------------- GN + SiLU in place
__global__ void k_gnsilu(float* __restrict__ buf,
                         const float* __restrict__ gg, const float* __restrict__ gb) {
    int idx = blockIdx.x * 256 + threadIdx.x;
    int c = (idx >> 15) & 63, b = idx >> 21;
    int bg = b * NG + (c >> 3);
    float x = buf[idx];
    x = (x - g_mu[bg]) * g_rs[bg] * gg[c] + gb[c];
    buf[idx] = siluf(x);
}

// ---------------- GN3 + SiLU + transpose (b,c,v) -> (b,v,c) into g_buf3
__global__ void k_gnsilu_tr(const float* __restrict__ gg, const float* __restrict__ gb) {
    __shared__ float s[64 * 33];
    int b = blockIdx.y;
    int v0 = blockIdx.x << 5;
    int tid = threadIdx.x;
    #pragma unroll
    for (int k = 0; k < 8; k++) {
        int i = tid + (k << 8);
        int c = i >> 5, v = i & 31;
        float x = g_buf2[((b * CC + c) << 15) + v0 + v];
        int bg = b * NG + (c >> 3);
        x = (x - g_mu[bg]) * g_rs[bg] * gg[c] + gb[c];
        s[c * 33 + v] = siluf(x);
    }
    __syncthreads();
    #pragma unroll
    for (int k = 0; k < 8; k++) {
        int i = tid + (k << 8);
        int v = i >> 6, c = i & 63;
        g_buf3[(((b << 15) + v0 + v) << 6) + c] = s[c * 33 + v];
    }
}

// ---------------- devoxelize (trilinear) + fuse GEMM -> out_pre in g_buf1
__global__ void __launch_bounds__(128) k_devox(const float* __restrict__ coords,
                                               const float* __restrict__ wfuse) {
    __shared__ float4 swf[64 * 16];                 // transposed [c][o/4]
    for (int i = threadIdx.x; i < CC * CC; i += 128) {
        int o = i >> 6, c = i & 63;
        ((float*)swf)[(c << 6) + o] = wfuse[i];
    }
    __syncthreads();
    int p = blockIdx.x * 128 + threadIdx.x;
    int b = p >> 15, n = p & 32767;
    float cx = coords[p * 3 + 0] * 31.f;
    float cy = coords[p * 3 + 1] * 31.f;
    float cz = coords[p * 3 + 2] * 31.f;
    float fx = cx - floorf(cx), fy = cy - floorf(cy), fz = cz - floorf(cz);
    int x0 = min(max(__float2int_rd(cx), 0), 31); int x1 = min(x0 + 1, 31);
    int y0 = min(max(__float2int_rd(cy), 0), 31); int y1 = min(y0 + 1, 31);
    int z0 = min(max(__float2int_rd(cz), 0), 31); int z1 = min(z0 + 1, 31);
    float wx0 = 1.f - fx, wy0 = 1.f - fy, wz0 = 1.f - fz;

    const float4* base[8];
    float wk[8];
    int k = 0;
    #pragma unroll
    for (int dx = 0; dx < 2; dx++)
        #pragma unroll
        for (int dy = 0; dy < 2; dy++)
            #pragma unroll
            for (int dz = 0; dz < 2; dz++) {
                int X = dx ? x1 : x0, Y = dy ? y1 : y0, Z = dz ? z1 : z0;
                wk[k] = (dx ? fx : wx0) * (dy ? fy : wy0) * (dz ? fz : wz0);
                base[k] = (const float4*)(g_buf3 + (((b << 15) + ((X << 10) + (Y << 5) + Z)) << 6));
                k++;
            }

    float acc[CC];
    #pragma unroll
    for (int o = 0; o < CC; o++) acc[o] = 0.f;

    #pragma unroll
    for (int c4 = 0; c4 < 16; c4++) {
        float r[32];
        #pragma unroll
        for (int kk = 0; kk < 8; kk++) {
            float4 v = __ldg(base[kk] + c4);
            r[kk * 4 + 0] = v.x; r[kk * 4 + 1] = v.y; r[kk * 4 + 2] = v.z; r[kk * 4 + 3] = v.w;
        }
        #pragma unroll
        for (int j = 0; j < 4; j++) {
            float d = r[j] * wk[0] + r[4 + j] * wk[1] + r[8 + j] * wk[2] + r[12 + j] * wk[3]
                    + r[16 + j] * wk[4] + r[20 + j] * wk[5] + r[24 + j] * wk[6] + r[28 + j] * wk[7];
            const float4* wr = swf + ((c4 * 4 + j) << 4);
            #pragma unroll
            for (int q = 0; q < 16; q++) {
                float4 ww = wr[q];
                acc[q * 4 + 0] += d * ww.x; acc[q * 4 + 1] += d * ww.y;
                acc[q * 4 + 2] += d * ww.z; acc[q * 4 + 3] += d * ww.w;
            }
        }
    }
    #pragma unroll
    for (int o = 0; o < CC; o++) g_buf1[((b * CC + o) << 15) + n] = acc[o];
}

// ---------------- final: out = silu(GN4(out_pre)) + w_skip @ feats
__global__ void __launch_bounds__(128) k_final(const float* __restrict__ feats,
                                               const float* __restrict__ wskip,
                                               const float* __restrict__ gg,
                                               const float* __restrict__ gb,
                                               float* __restrict__ out) {
    __shared__ float4 sw[CIN * 16];
    __shared__ float sg[64], sb2[64];
    for (int i = threadIdx.x; i < CIN * CC; i += 128) {
        int o = i >> 5, c = i & 31;
        ((float*)sw)[c * CC + o] = wskip[i];
    }
    if (threadIdx.x < 64) { sg[threadIdx.x] = gg[threadIdx.x]; sb2[threadIdx.x] = gb[threadIdx.x]; }
    __syncthreads();
    int p = blockIdx.x * 128 + threadIdx.x;
    int b = p >> 15, n = p & 32767;
    float acc[CC];
    #pragma unroll
    for (int o = 0; o < CC; o++) acc[o] = 0.f;
    #pragma unroll 4
    for (int c = 0; c < CIN; c++) {
        float x = feats[((b * CIN + c) << 15) + n];
        const float4* wr = sw + c * 16;
        #pragma unroll
        for (int q = 0; q < 16; q++) {
            float4 ww = wr[q];
            acc[q * 4 + 0] += x * ww.x; acc[q * 4 + 1] += x * ww.y;
            acc[q * 4 + 2] += x * ww.z; acc[q * 4 + 3] += x * ww.w;
        }
    }
    #pragma unroll
    for (int o = 0; o < CC; o++) {
        int bg = b * NG + (o >> 3);
        float v = g_buf1[((b * CC + o) << 15) + n];
        v = (v - g_mu[bg]) * g_rs[bg] * sg[o] + sb2[o];
        out[((b * CC + o) << 15) + n] = siluf(v) + acc[o];
    }
}

// ---------------------------------------------------------------------------
extern "C" void kernel_launch(void* const* d_in, const int* in_sizes, int n_in,
                              void* d_out, int out_size) {
    const float* feats  = (const float*)d_in[0];
    const float* coords = (const float*)d_in[1];
    const float* t_emb  = (const float*)d_in[2];
    const float* w_in   = (const float*)d_in[3];
    const float* gn1_g  = (const float*)d_in[4];
    const float* gn1_b  = (const float*)d_in[5];
    const float* w_time = (const float*)d_in[6];
    const float* b_time = (const float*)d_in[7];
    const float* w_vox1 = (const float*)d_in[8];
    const float* gn2_g  = (const float*)d_in[9];
    const float* gn2_b  = (const float*)d_in[10];
    const float* w_vox2 = (const float*)d_in[11];
    const float* gn3_g  = (const float*)d_in[12];
    const float* gn3_b  = (const float*)d_in[13];
    const float* w_fuse = (const float*)d_in[14];
    const float* gn4_g  = (const float*)d_in[15];
    const float* gn4_b  = (const float*)d_in[16];
    const float* w_skip = (const float*)d_in[17];
    float* out = (float*)d_out;

    float *b1, *b2, *b3;
    cudaGetSymbolAddress((void**)&b1, g_buf1);
    cudaGetSymbolAddress((void**)&b2, g_buf2);
    cudaGetSymbolAddress((void**)&b3, g_buf3);

    k_bias<<<NB, 64>>>(t_emb, w_time, b_time);
    k_pw_in<<<1024, 128>>>(feats, w_in);
    k_stats<<<32, 256>>>(b1);                          // GN1 stats
    k_zero<<<32768, 256>>>();
    k_scatter<<<1024, 128>>>(coords, gn1_g, gn1_b);    // GN1+SiLU+bias, scatter
    k_voxfin<<<32768, 256>>>();                        // mean + bias -> vox0 (b2)
    k_conv<<<dim3(64, 4, 4), 128>>>(b2, w_vox1, b3);   // conv1 -> b3
    k_stats<<<32, 256>>>(b3);                          // GN2 stats
    k_gnsilu<<<32768, 256>>>(b3, gn2_g, gn2_b);        // GN2+SiLU in place
    k_conv<<<dim3(64, 4, 4), 128>>>(b3, w_vox2, b2);   // conv2 -> b2
    k_stats<<<32, 256>>>(b2);                          // GN3 stats
    k_gnsilu_tr<<<dim3(1024, NB), 256>>>(gn3_g, gn3_b);// GN3+SiLU + transpose -> b3 (b,v,c)
    k_devox<<<1024, 128>>>(coords, w_fuse);            // trilinear + fuse -> b1
    k_stats<<<32, 256>>>(b1);                          // GN4 stats
    k_final<<<1024, 128>>>(feats, w_skip, gn4_g, gn4_b, out);
}

// round 4
// speedup vs baseline: 1.8373x; 1.8373x over previous
#include <cuda_runtime.h>
#include <cuda_fp16.h>
#include <cstdint>

#define NB   4
#define CIN  32
#define CC   64
#define V3   32768
#define NG   8
#define EPS  1e-5f

__device__ __align__(16) float g_pts[NB * CC * V3];
__device__ __align__(16) float g_vox_a[NB * V3 * CC];
__device__ __align__(16) float g_vox_b[NB * V3 * CC];
__device__ __align__(16) __half g_hi[NB * V3 * CC];
__device__ __align__(16) __half g_lo[NB * V3 * CC];
__device__ __align__(16) unsigned char g_wblob[884736];  // [conv][prec][tap][64x128B sw128]
__device__ int   g_cnt[NB * V3];
__device__ float g_bias[NB * CC];
__device__ float g_mu[NB * NG];
__device__ float g_rs[NB * NG];

__device__ __forceinline__ float siluf(float x) { return x / (1.f + __expf(-x)); }

__device__ __forceinline__ uint32_t s2u(const void* p) {
    uint32_t a;
    asm("{ .reg .u64 t; cvta.to.shared.u64 t, %1; cvt.u32.u64 %0, t; }" : "=r"(a) : "l"(p));
    return a;
}

#define LDSM4(R, addr) \
    asm volatile("ldmatrix.sync.aligned.m8n8.x4.shared.b16 {%0,%1,%2,%3}, [%4];" \
        : "=r"((R)[0]), "=r"((R)[1]), "=r"((R)[2]), "=r"((R)[3]) : "r"(addr))
#define LDSM4T(r0, r1, r2, r3, addr) \
    asm volatile("ldmatrix.sync.aligned.m8n8.x4.trans.shared.b16 {%0,%1,%2,%3}, [%4];" \
        : "=r"(r0), "=r"(r1), "=r"(r2), "=r"(r3) : "r"(addr))
#define MMA(dacc, A, B) \
    asm volatile("mma.sync.aligned.m16n8k16.row.col.f32.f16.f16.f32 " \
        "{%0,%1,%2,%3}, {%4,%5,%6,%7}, {%8,%9}, {%0,%1,%2,%3};" \
        : "+f"((dacc)[0]), "+f"((dacc)[1]), "+f"((dacc)[2]), "+f"((dacc)[3]) \
        : "r"((A)[0]), "r"((A)[1]), "r"((A)[2]), "r"((A)[3]), "r"((B)[0]), "r"((B)[1]))

__device__ __forceinline__ void hi_lo(float v, unsigned short& h, unsigned short& l) {
    __half hb = __float2half_rn(v);
    h = __half_as_ushort(hb);
    l = __half_as_ushort(__float2half_rn(v - __half2float(hb)));
}

// ---------------- small kernels ----------------
__global__ void k_bias(const float* __restrict__ te_, const float* __restrict__ wt,
                       const float* __restrict__ bt) {
    __shared__ float te[256];
    int b = blockIdx.x, o = threadIdx.x;
    for (int i = o; i < 256; i += 64) te[i] = te_[b * 256 + i];
    __syncthreads();
    float s = bt[o];
    #pragma unroll 8
    for (int t = 0; t < 256; t++) s += te[t] * wt[o * 256 + t];
    g_bias[b * CC + o] = s;
}

__global__ void __launch_bounds__(128) k_pw_in(const float* __restrict__ f, const float* __restrict__ w) {
    __shared__ float sw[CIN * CC];
    for (int i = threadIdx.x; i < CIN * CC; i += 128) sw[(i & 31) * CC + (i >> 5)] = w[i];
    __syncthreads();
    int p = blockIdx.x * 128 + threadIdx.x;
    int b = p >> 15, n = p & 32767;
    float acc[CC];
    #pragma unroll
    for (int o = 0; o < CC; o++) acc[o] = 0.f;
    for (int c = 0; c < CIN; c++) {
        float x = f[((b * CIN + c) << 15) + n];
        const float4* wr = (const float4*)(sw + c * CC);
        #pragma unroll
        for (int q = 0; q < 16; q++) {
            float4 ww = wr[q];
            acc[q*4+0] += x*ww.x; acc[q*4+1] += x*ww.y; acc[q*4+2] += x*ww.z; acc[q*4+3] += x*ww.w;
        }
    }
    #pragma unroll
    for (int o = 0; o < CC; o++) g_pts[((b * CC + o) << 15) + n] = acc[o];
}

__global__ void k_stats(const float* __restrict__ buf) {   // (b,c,n) contiguous groups
    __shared__ float ss[256], sq[256];
    int bg = blockIdx.x;
    const float4* p = (const float4*)(buf + (size_t)bg * 262144);
    float s = 0.f, q = 0.f;
    for (int i = threadIdx.x; i < 65536; i += 256) {
        float4 v = p[i];
        s += v.x + v.y + v.z + v.w;
        q += v.x*v.x + v.y*v.y + v.z*v.z + v.w*v.w;
    }
    ss[threadIdx.x] = s; sq[threadIdx.x] = q; __syncthreads();
    for (int st = 128; st > 0; st >>= 1) {
        if (threadIdx.x < st) { ss[threadIdx.x] += ss[threadIdx.x+st]; sq[threadIdx.x] += sq[threadIdx.x+st]; }
        __syncthreads();
    }
    if (threadIdx.x == 0) {
        float m = ss[0] * (1.f/262144.f), v = sq[0] * (1.f/262144.f) - m*m;
        g_mu[bg] = m; g_rs[bg] = rsqrtf(v + EPS);
    }
}

__global__ void k_stats_vc(const float* __restrict__ buf) {  // (b,v,c)
    __shared__ float ss[256], sq[256];
    int bg = blockIdx.x, b = bg >> 3, g = bg & 7;
    const float4* base = (const float4*)(buf + ((size_t)b << 21) + (g << 3));
    float s = 0.f, q = 0.f;
    for (int v = threadIdx.x; v < V3; v += 256) {
        float4 a = base[(size_t)v * 16], c = base[(size_t)v * 16 + 1];
        s += a.x+a.y+a.z+a.w + c.x+c.y+c.z+c.w;
        q += a.x*a.x+a.y*a.y+a.z*a.z+a.w*a.w + c.x*c.x+c.y*c.y+c.z*c.z+c.w*c.w;
    }
    ss[threadIdx.x] = s; sq[threadIdx.x] = q; __syncthreads();
    for (int st = 128; st > 0; st >>= 1) {
        if (threadIdx.x < st) { ss[threadIdx.x] += ss[threadIdx.x+st]; sq[threadIdx.x] += sq[threadIdx.x+st]; }
        __syncthreads();
    }
    if (threadIdx.x == 0) {
        float m = ss[0] * (1.f/262144.f), v = sq[0] * (1.f/262144.f) - m*m;
        g_mu[bg] = m; g_rs[bg] = rsqrtf(v + EPS);
    }
}

__global__ void k_zero() {
    int idx = blockIdx.x * 256 + threadIdx.x;           // 2097152 float4
    ((float4*)g_vox_a)[idx] = make_float4(0.f,0.f,0.f,0.f);
    if (idx < NB * V3) g_cnt[idx] = 0;
}

__global__ void __launch_bounds__(128) k_scatter(const float* __restrict__ coords,
                                                 const float* __restrict__ gg,
                                                 const float* __restrict__ gb) {
    int p = blockIdx.x * 128 + threadIdx.x;
    int b = p >> 15, n = p & 32767;
    int ix = min(max(__float2int_rd(coords[p*3+0]*31.f), 0), 31);
    int iy = min(max(__float2int_rd(coords[p*3+1]*31.f), 0), 31);
    int iz = min(max(__float2int_rd(coords[p*3+2]*31.f), 0), 31);
    int flat = (ix << 10) + (iy << 5) + iz;
    atomicAdd(&g_cnt[(b << 15) + flat], 1);
    float* dst = g_vox_a + ((size_t)((b << 15) + flat) << 6);
    #pragma unroll 4
    for (int c = 0; c < CC; c++) {
        int bg = b * NG + (c >> 3);
        float x = g_pts[((b * CC + c) << 15) + n];
        x = siluf((x - g_mu[bg]) * g_rs[bg] * gg[c] + gb[c]) + g_bias[b * CC + c];
        atomicAdd(dst + c, x);
    }
}

__global__ void k_voxfin_cvt() {
    int idx = blockIdx.x * 256 + threadIdx.x;           // b*V3+v
    int b = idx >> 15;
    float inv = 1.f / (float)max(g_cnt[idx], 1);
    const float4* s4 = (const float4*)(g_vox_a + ((size_t)idx << 6));
    uint4* h4 = (uint4*)(g_hi + ((size_t)idx << 6));
    uint4* l4 = (uint4*)(g_lo + ((size_t)idx << 6));
    const float* bias = g_bias + b * CC;
    #pragma unroll
    for (int q = 0; q < 8; q++) {
        float4 v0 = s4[q*2], v1 = s4[q*2+1];
        float x[8] = {v0.x,v0.y,v0.z,v0.w,v1.x,v1.y,v1.z,v1.w};
        unsigned short hs[8], ls[8];
        #pragma unroll
        for (int j = 0; j < 8; j++) hi_lo(x[j]*inv + bias[q*8+j], hs[j], ls[j]);
        h4[q] = make_uint4(hs[0]|((uint32_t)hs[1]<<16), hs[2]|((uint32_t)hs[3]<<16),
                           hs[4]|((uint32_t)hs[5]<<16), hs[6]|((uint32_t)hs[7]<<16));
        l4[q] = make_uint4(ls[0]|((uint32_t)ls[1]<<16), ls[2]|((uint32_t)ls[3]<<16),
                           ls[4]|((uint32_t)ls[5]<<16), ls[6]|((uint32_t)ls[7]<<16));
    }
}

__global__ void k_gnsilu_cvt(const float* __restrict__ src,
                             const float* __restrict__ gg, const float* __restrict__ gb) {
    int idx = blockIdx.x * 256 + threadIdx.x;
    int b = idx >> 15;
    const float4* s4 = (const float4*)(src + ((size_t)idx << 6));
    uint4* h4 = (uint4*)(g_hi + ((size_t)idx << 6));
    uint4* l4 = (uint4*)(g_lo + ((size_t)idx << 6));
    #pragma unroll
    for (int q = 0; q < 8; q++) {
        float mu = g_mu[b*NG+q], rs = g_rs[b*NG+q];
        float4 v0 = s4[q*2], v1 = s4[q*2+1];
        float x[8] = {v0.x,v0.y,v0.z,v0.w,v1.x,v1.y,v1.z,v1.w};
        unsigned short hs[8], ls[8];
        #pragma unroll
        for (int j = 0; j < 8; j++) {
            int c = q*8+j;
            hi_lo(siluf((x[j]-mu)*rs*gg[c] + gb[c]), hs[j], ls[j]);
        }
        h4[q] = make_uint4(hs[0]|((uint32_t)hs[1]<<16), hs[2]|((uint32_t)hs[3]<<16),
                           hs[4]|((uint32_t)hs[5]<<16), hs[6]|((uint32_t)hs[7]<<16));
        l4[q] = make_uint4(ls[0]|((uint32_t)ls[1]<<16), ls[2]|((uint32_t)ls[3]<<16),
                           ls[4]|((uint32_t)ls[5]<<16), ls[6]|((uint32_t)ls[7]<<16));
    }
}

__global__ void k_gnsilu_vc(float* __restrict__ buf,
                            const float* __restrict__ gg, const float* __restrict__ gb) {
    int idx = blockIdx.x * 256 + threadIdx.x;
    int b = idx >> 15;
    float4* s4 = (float4*)(buf + ((size_t)idx << 6));
    #pragma unroll
    for (int q = 0; q < 8; q++) {
        float mu = g_mu[b*NG+q], rs = g_rs[b*NG+q];
        float4 v0 = s4[q*2], v1 = s4[q*2+1];
        float x[8] = {v0.x,v0.y,v0.z,v0.w,v1.x,v1.y,v1.z,v1.w};
        #pragma unroll
        for (int j = 0; j < 8; j++) {
            int c = q*8+j;
            x[j] = siluf((x[j]-mu)*rs*gg[c] + gb[c]);
        }
        s4[q*2]   = make_float4(x[0],x[1],x[2],x[3]);
        s4[q*2+1] = make_float4(x[4],x[5],x[6],x[7]);
    }
}

// wblob: B matrix per tap: row k = c_in (64 rows x 128B), col n = o_out, SW128 swizzled.
__global__ void k_wprep(const float* __restrict__ w1, const float* __restrict__ w2) {
    int i = blockIdx.x * 256 + threadIdx.x;
    if (i >= 221184) return;
    int conv = i / 110592, r = i - conv * 110592;
    int o = r / 1728, r2 = r - o * 1728;
    int c = r2 / 27, t = r2 - c * 27;
    float w = conv ? w2[r] : w1[r];
    __half h = __float2half_rn(w);
    __half l = __float2half_rn(w - __half2float(h));
    uint32_t off = (uint32_t)c * 128 + (uint32_t)o * 2;
    uint32_t swo = off ^ ((off >> 3) & 0x70);
    size_t base = (size_t)conv * 442368;
    *(__half*)(g_wblob + base + (size_t)t * 8192 + swo) = h;
    *(__half*)(g_wblob + base + 221184 + (size_t)t * 8192 + swo) = l;
}

// ---------------- HMMA conv: mma.sync m16n8k16 f16, 3-pass hi/lo ----------------
// smem: A slab hi [0, 26112) = 204 rows(6y x 34x) x 128B; A lo [26112, 52224);
//       W hi [52224, 60416); W lo [60416, 68608)
#define CONV_SMEM 68608

__global__ void __launch_bounds__(128)
k_conv_mma(const __half* __restrict__ hi, const __half* __restrict__ lo,
           const unsigned char* __restrict__ wblob, float* __restrict__ out) {
    extern __shared__ char smem[];
    const uint32_t sb = s2u(smem);
    const int tid = threadIdx.x, wid = tid >> 5, lane = tid & 31;
    int t = blockIdx.x;                     // b*256 + d*8 + hg
    int b = t >> 8, tt = t & 255;
    int d = tt >> 3, h0 = (tt & 7) << 2;
    int r0 = t << 7;                        // base output voxel index (b,v)

    float acc[2][8][4];
    #pragma unroll
    for (int mt = 0; mt < 2; mt++)
        #pragma unroll
        for (int nt = 0; nt < 8; nt++)
            #pragma unroll
            for (int k = 0; k < 4; k++) acc[mt][nt][k] = 0.f;

    const int a_r  = lane & 15;
    const int a_cb = (lane >> 4) << 4;

    for (int dz = 0; dz < 3; dz++) {
        int dp = d + dz - 1;
        if ((unsigned)dp >= 32u) continue;
        __syncthreads();
        // stage A slab: rows = (yy+1)*34 + (x+1), yy in -1..4, x in -1..32
        for (int i = tid; i < 3264; i += 128) {
            int prec = (i >= 1632) ? 1 : 0;
            int j = prec ? i - 1632 : i;
            int row = j >> 3, c16 = j & 7;
            int yyl = row / 34, xl = row - yyl * 34;
            int hh = h0 + yyl - 1, ww = xl - 1;
            uint4 v = make_uint4(0, 0, 0, 0);
            if ((unsigned)hh < 32u && (unsigned)ww < 32u) {
                size_t g = ((size_t)((b << 15) + (dp << 10) + (hh << 5) + ww) << 3) + c16;
                v = prec ? ((const uint4*)lo)[g] : ((const uint4*)hi)[g];
            }
            *(uint4*)(smem + prec * 26112 + row * 128 + ((c16 << 4) ^ ((row & 7) << 4))) = v;
        }
        for (int t9 = 0; t9 < 9; t9++) {
            int tap = dz * 9 + t9;
            __syncthreads();
            {   // stage W (pre-swizzled): 512 uint4 hi + 512 uint4 lo
                const uint4* wsh = (const uint4*)(wblob + (size_t)tap * 8192);
                const uint4* wsl = (const uint4*)(wblob + 221184 + (size_t)tap * 8192);
                uint4* wd = (uint4*)(smem + 52224);
                #pragma unroll
                for (int k = 0; k < 4; k++) {
                    wd[tid + (k << 7)] = wsh[tid + (k << 7)];
                    wd[512 + tid + (k << 7)] = wsl[tid + (k << 7)];
                }
            }
            __syncthreads();
            int dy = t9 / 3 - 1, dx = t9 - (t9 / 3) * 3 - 1;
            int srow_base = (wid + dy + 1) * 34 + (dx + 1);
            #pragma unroll
            for (int ks = 0; ks < 4; ks++) {
                uint32_t Ah[2][4], Al[2][4], Bh[8][2], Bl[8][2];
                int cb = (ks << 5) + a_cb;
                #pragma unroll
                for (int mt = 0; mt < 2; mt++) {
                    int row = srow_base + (mt << 4) + a_r;
                    uint32_t sw = (uint32_t)(cb ^ ((row & 7) << 4));
                    uint32_t addr = sb + (uint32_t)row * 128 + sw;
                    LDSM4(Ah[mt], addr);
                    LDSM4(Al[mt], addr + 26112);
                }
                {
                    int krow = (ks << 4) + (lane & 15);
                    uint32_t rbase = sb + 52224 + (uint32_t)krow * 128;
                    uint32_t xr = (uint32_t)((krow & 7) << 4);
                    int nbl = (lane >> 4) << 4;
                    #pragma unroll
                    for (int nt4 = 0; nt4 < 4; nt4++) {
                        uint32_t nb = (uint32_t)((nt4 << 5) + nbl);
                        uint32_t addr = rbase + (nb ^ xr);
                        LDSM4T(Bh[nt4*2][0], Bh[nt4*2][1], Bh[nt4*2+1][0], Bh[nt4*2+1][1], addr);
                        LDSM4T(Bl[nt4*2][0], Bl[nt4*2][1], Bl[nt4*2+1][0], Bl[nt4*2+1][1], addr + 8192);
                    }
                }
                #pragma unroll
                for (int mt = 0; mt < 2; mt++)
                    #pragma unroll
                    for (int nt = 0; nt < 8; nt++) {
                        MMA(acc[mt][nt], Ah[mt], Bh[nt]);
                        MMA(acc[mt][nt], Ah[mt], Bl[nt]);
                        MMA(acc[mt][nt], Al[mt], Bh[nt]);
                    }
            }
        }
    }
    // epilogue: write fp32 (b,v,c)
    int g = lane >> 2, tg = lane & 3;
    #pragma unroll
    for (int mt = 0; mt < 2; mt++) {
        int v0 = r0 + (wid << 5) + (mt << 4) + g;
        #pragma unroll
        for (int nt = 0; nt < 8; nt++) {
            int c = (nt << 3) + tg * 2;
            float* o = out + ((size_t)v0 << 6) + c;
            o[0] = acc[mt][nt][0];
            o[1] = acc[mt][nt][1];
            o[512] = acc[mt][nt][2];      // row +8 -> +8*64 floats
            o[513] = acc[mt][nt][3];
        }
    }
}

// ---------------- devox + fuse ----------------
__global__ void __launch_bounds__(128) k_devox(const float* __restrict__ coords,
                                               const float* __restrict__ wfuse) {
    __shared__ float swf[CC * CC];
    for (int i = threadIdx.x; i < CC * CC; i += 128) swf[(i & 63) * CC + (i >> 6)] = wfuse[i];
    __syncthreads();
    int p = blockIdx.x * 128 + threadIdx.x;
    int b = p >> 15, n = p & 32767;
    float cx = coords[p*3+0]*31.f, cy = coords[p*3+1]*31.f, cz = coords[p*3+2]*31.f;
    float fx = cx - floorf(cx), fy = cy - floorf(cy), fz = cz - floorf(cz);
    int x0 = min(max(__float2int_rd(cx),0),31), x1 = min(x0+1,31);
    int y0 = min(max(__float2int_rd(cy),0),31), y1 = min(y0+1,31);
    int z0 = min(max(__float2int_rd(cz),0),31), z1 = min(z0+1,31);
    const float4* base[8]; float wk[8]; int k = 0;
    #pragma unroll
    for (int ddx = 0; ddx < 2; ddx++)
        #pragma unroll
        for (int ddy = 0; ddy < 2; ddy++)
            #pragma unroll
            for (int ddz = 0; ddz < 2; ddz++) {
                int X = ddx?x1:x0, Y = ddy?y1:y0, Z = ddz?z1:z0;
                wk[k] = (ddx?fx:1.f-fx)*(ddy?fy:1.f-fy)*(ddz?fz:1.f-fz);
                base[k] = (const float4*)(g_vox_b + (((size_t)(b<<15) + ((X<<10)+(Y<<5)+Z)) << 6));
                k++;
            }
    float acc[CC];
    #pragma unroll
    for (int o = 0; o < CC; o++) acc[o] = 0.f;
    #pragma unroll
    for (int c4 = 0; c4 < 16; c4++) {
        float r[32];
        #pragma unroll
        for (int kk = 0; kk < 8; kk++) {
            float4 v = __ldg(base[kk] + c4);
            r[kk*4] = v.x; r[kk*4+1] = v.y; r[kk*4+2] = v.z; r[kk*4+3] = v.w;
        }
        #pragma unroll
        for (int j = 0; j < 4; j++) {
            float dd = r[j]*wk[0] + r[4+j]*wk[1] + r[8+j]*wk[2] + r[12+j]*wk[3]
                     + r[16+j]*wk[4] + r[20+j]*wk[5] + r[24+j]*wk[6] + r[28+j]*wk[7];
            const float4* wr = (const float4*)(swf + (c4*4+j)*CC);
            #pragma unroll
            for (int q = 0; q < 16; q++) {
                float4 ww = wr[q];
                acc[q*4+0] += dd*ww.x; acc[q*4+1] += dd*ww.y; acc[q*4+2] += dd*ww.z; acc[q*4+3] += dd*ww.w;
            }
        }
    }
    #pragma unroll
    for (int o = 0; o < CC; o++) g_pts[((b * CC + o) << 15) + n] = acc[o];
}

__global__ void __launch_bounds__(128) k_final(const float* __restrict__ f,
                                               const float* __restrict__ wskip,
                                               const float* __restrict__ gg,
                                               const float* __restrict__ gb,
                                               float* __restrict__ out) {
    __shared__ float sw[CIN * CC];
    __shared__ float sg[64], sb2[64];
    for (int i = threadIdx.x; i < CIN * CC; i += 128) sw[(i & 31) * CC + (i >> 5)] = wskip[i];
    if (threadIdx.x < 64) { sg[threadIdx.x] = gg[threadIdx.x]; sb2[threadIdx.x] = gb[threadIdx.x]; }
    __syncthreads();
    int p = blockIdx.x * 128 + threadIdx.x;
    int b = p >> 15, n = p & 32767;
    float acc[CC];
    #pragma unroll
    for (int o = 0; o < CC; o++) acc[o] = 0.f;
    for (int c = 0; c < CIN; c++) {
        float x = f[((b * CIN + c) << 15) + n];
        const float4* wr = (const float4*)(sw + c * CC);
        #pragma unroll
        for (int q = 0; q < 16; q++) {
            float4 ww = wr[q];
            acc[q*4+0] += x*ww.x; acc[q*4+1] += x*ww.y; acc[q*4+2] += x*ww.z; acc[q*4+3] += x*ww.w;
        }
    }
    #pragma unroll
    for (int o = 0; o < CC; o++) {
        int bg = b * NG + (o >> 3);
        float v = g_pts[((b * CC + o) << 15) + n];
        v = (v - g_mu[bg]) * g_rs[bg] * sg[o] + sb2[o];
        out[((b * CC + o) << 15) + n] = siluf(v) + acc[o];
    }
}

// ---------------------------------------------------------------------------
extern "C" void kernel_launch(void* const* d_in, const int* in_sizes, int n_in,
                              void* d_out, int out_size) {
    const float* feats  = (const float*)d_in[0];
    const float* coords = (const float*)d_in[1];
    const float* t_emb  = (const float*)d_in[2];
    const float* w_in   = (const float*)d_in[3];
    const float* gn1_g  = (const float*)d_in[4];
    const float* gn1_b  = (const float*)d_in[5];
    const float* w_time = (const float*)d_in[6];
    const float* b_time = (const float*)d_in[7];
    const float* w_vox1 = (const float*)d_in[8];
    const float* gn2_g  = (const float*)d_in[9];
    const float* gn2_b  = (const float*)d_in[10];
    const float* w_vox2 = (const float*)d_in[11];
    const float* gn3_g  = (const float*)d_in[12];
    const float* gn3_b  = (const float*)d_in[13];
    const float* w_fuse = (const float*)d_in[14];
    const float* gn4_g  = (const float*)d_in[15];
    const float* gn4_b  = (const float*)d_in[16];
    const float* w_skip = (const float*)d_in[17];
    float* out = (float*)d_out;

    float *pts, *va, *vb;
    __half *hp, *lp;
    unsigned char* wb;
    cudaGetSymbolAddress((void**)&pts, g_pts);
    cudaGetSymbolAddress((void**)&va, g_vox_a);
    cudaGetSymbolAddress((void**)&vb, g_vox_b);
    cudaGetSymbolAddress((void**)&hp, g_hi);
    cudaGetSymbolAddress((void**)&lp, g_lo);
    cudaGetSymbolAddress((void**)&wb, g_wblob);

    static int attr_set = 0;
    if (!attr_set) {
        cudaFuncSetAttribute(k_conv_mma, cudaFuncAttributeMaxDynamicSharedMemorySize, CONV_SMEM);
        attr_set = 1;
    }

    k_bias<<<NB, 64>>>(t_emb, w_time, b_time);
    k_wprep<<<864, 256>>>(w_vox1, w_vox2);
    k_pw_in<<<1024, 128>>>(feats, w_in);
    k_stats<<<32, 256>>>(pts);
    k_zero<<<8192, 256>>>();
    k_scatter<<<1024, 128>>>(coords, gn1_g, gn1_b);
    k_voxfin_cvt<<<512, 256>>>();
    k_conv_mma<<<1024, 128, CONV_SMEM>>>(hp, lp, wb, va);
    k_stats_vc<<<32, 256>>>(va);
    k_gnsilu_cvt<<<512, 256>>>(va, gn2_g, gn2_b);
    k_conv_mma<<<1024, 128, CONV_SMEM>>>(hp, lp, wb + 442368, vb);
    k_stats_vc<<<32, 256>>>(vb);
    k_gnsilu_vc<<<512, 256>>>(vb, gn3_g, gn3_b);
    k_devox<<<1024, 128>>>(coords, w_fuse);
    k_stats<<<32, 256>>>(pts);
    k_final<<<1024, 128>>>(feats, w_skip, gn4_g, gn4_b, out);
}